// round 3
// baseline (speedup 1.0000x reference)
#include <cuda_runtime.h>
#include <cuda_bf16.h>
#include <cuda_fp16.h>
#include <cstdint>

// MX quantize-dequantize, block=32 contiguous floats.
// Each thread owns 8 contiguous floats (one 256-bit ld/st); a 32-block spans
// 4 adjacent lanes -> 2 butterfly shuffles for the block amax. Quantize core
// is the HW e4m3 converter (RNE + satfinite + denormals == reference's
// mbits=5/ebits=4/max_norm=448 semantics, validated at rel_err 1e-4 in R1/R2).

__device__ __forceinline__ float block_scale(float amax) {
    // bf16-exact: s = floor(bf16(bf16(amax/448)*256 + 0.5))/256 ; 0 -> 1
    float sc = __bfloat162float(__float2bfloat16(amax * (1.0f / 448.0f)));
    float u  = __bfloat162float(__float2bfloat16(sc * 256.0f + 0.5f));
    float s  = floorf(u) * (1.0f / 256.0f);
    return (s == 0.0f) ? 1.0f : s;
}

__device__ __forceinline__ void ld256(const float* p, float* v) {
    uint32_t a, b, c, d, e, f, g, h;
    asm volatile("ld.global.cs.v8.b32 {%0,%1,%2,%3,%4,%5,%6,%7}, [%8];"
                 : "=r"(a), "=r"(b), "=r"(c), "=r"(d),
                   "=r"(e), "=r"(f), "=r"(g), "=r"(h)
                 : "l"(p));
    v[0] = __uint_as_float(a); v[1] = __uint_as_float(b);
    v[2] = __uint_as_float(c); v[3] = __uint_as_float(d);
    v[4] = __uint_as_float(e); v[5] = __uint_as_float(f);
    v[6] = __uint_as_float(g); v[7] = __uint_as_float(h);
}

__device__ __forceinline__ void st256(float* p, const float* v) {
    asm volatile("st.global.cs.v8.b32 [%0], {%1,%2,%3,%4,%5,%6,%7,%8};"
                 :: "l"(p),
                    "r"(__float_as_uint(v[0])), "r"(__float_as_uint(v[1])),
                    "r"(__float_as_uint(v[2])), "r"(__float_as_uint(v[3])),
                    "r"(__float_as_uint(v[4])), "r"(__float_as_uint(v[5])),
                    "r"(__float_as_uint(v[6])), "r"(__float_as_uint(v[7]))
                 : "memory");
}

// Quantize-dequantize one pair via HW e4m3 converter: returns (q(a0), q(a1))*s
__device__ __forceinline__ void qdq_pair(float& x0, float& x1,
                                         float inv_s, float s) {
    float a0 = x0 * inv_s;
    float a1 = x1 * inv_s;
    uint16_t q;
    asm("cvt.rn.satfinite.e4m3x2.f32 %0, %1, %2;"
        : "=h"(q) : "f"(a1), "f"(a0));            // byte1=a1, byte0=a0
    uint32_t hh;
    asm("cvt.rn.f16x2.e4m3x2 %0, %1;" : "=r"(hh) : "h"(q));
    __half2 h2 = *reinterpret_cast<__half2*>(&hh); // h0=a0, h1=a1 (exact)
    float2 f2 = __half22float2(h2);
    x0 = f2.x * s;
    x1 = f2.y * s;
}

__device__ __forceinline__ void process8(float* v) {
    float m = fmaxf(fmaxf(fabsf(v[0]), fabsf(v[1])),
                    fmaxf(fabsf(v[2]), fabsf(v[3])));
    m = fmaxf(m, fmaxf(fmaxf(fabsf(v[4]), fabsf(v[5])),
                       fmaxf(fabsf(v[6]), fabsf(v[7]))));
    // 32-block = 4 adjacent lanes
    m = fmaxf(m, __shfl_xor_sync(0xffffffffu, m, 1));
    m = fmaxf(m, __shfl_xor_sync(0xffffffffu, m, 2));

    float s = block_scale(m);
    float inv_s = __frcp_rn(s);

    qdq_pair(v[0], v[1], inv_s, s);
    qdq_pair(v[2], v[3], inv_s, s);
    qdq_pair(v[4], v[5], inv_s, s);
    qdq_pair(v[6], v[7], inv_s, s);
}

__global__ __launch_bounds__(256) void mxq_kernel(const float* __restrict__ in,
                                                  float* __restrict__ out,
                                                  int nchunk) {
    const int UNROLL = 4;
    int base = blockIdx.x * (blockDim.x * UNROLL) + threadIdx.x;

    float v[UNROLL][8];
#pragma unroll
    for (int u = 0; u < UNROLL; u++) {
        int idx = base + u * blockDim.x;
        if (idx < nchunk) ld256(in + (size_t)idx * 8, v[u]);   // MLP=4
    }
#pragma unroll
    for (int u = 0; u < UNROLL; u++) {
        int idx = base + u * blockDim.x;
        if (idx < nchunk) {
            process8(v[u]);
            st256(out + (size_t)idx * 8, v[u]);
        }
    }
}

extern "C" void kernel_launch(void* const* d_in, const int* in_sizes, int n_in,
                              void* d_out, int out_size) {
    const float* x = (const float*)d_in[0];
    float* y = (float*)d_out;
    int n = in_sizes[0];              // 8192*8192 = 67,108,864
    int nchunk = n / 8;               // 8,388,608 chunks of 8 floats
    int threads = 256;
    int per_block = threads * 4;      // 4 chunks per thread
    int blocks = (nchunk + per_block - 1) / per_block;   // 8192 exactly
    mxq_kernel<<<blocks, threads>>>(x, y, nchunk);
}